// round 9
// baseline (speedup 1.0000x reference)
#include <cuda_runtime.h>

#define LROW 16384
#define N1 8199
#define N2 4107
#define N3 2061
#define N4 1038
#define ROWS_MAX 2048

// global scratch row strides (floats, multiples of 4)
#define S1 8200
#define S2 4112
#define S3 2064
#define S4 1040

__device__ float g_d1[(size_t)ROWS_MAX * S1];
__device__ float g_d2[(size_t)ROWS_MAX * S2];
__device__ float g_d3[(size_t)ROWS_MAX * S3];
__device__ float g_d4[(size_t)ROWS_MAX * S4];
__device__ float g_a4[(size_t)ROWS_MAX * S4];
__device__ float g_thr[ROWS_MAX];

// ---- fwd smem layout (floats) ----
// a1e [0,4104)  a1o [4104,8208)   (split a1, i -> a1[2i] / a1[2i+1])
// xe  [8208,10272) xo [10272,12336)   (staging; later a2e/a2o)
// a3e [0,1032) a3o [1040,2072)    (overlay dead a1 region)
#define F_A1E 0
#define F_A1O 4104
#define F_XE  8208
#define F_XO  10272
#define SM_FWD_FLOATS 12336
#define SM_FWD_BYTES  (SM_FWD_FLOATS * 4)

// ---- inv smem layout ----
#define SM_INV_FLOATS 12320
#define SM_INV_BYTES  (SM_INV_FLOATS * 4)
#define OFF_HI        8208

#define HLIT { \
    0.05441584224308161f,    0.3128715909144659f,    0.6756307362980128f, \
    0.5853546836548691f,    -0.015829105256023893f, -0.2840155429624281f, \
    0.00047248457399797254f, 0.128747426620186f,    -0.01736930100202211f, \
   -0.04408825393106472f,    0.013981027917015516f,  0.008746094047015655f, \
   -0.00487035299301066f,   -0.0003917403729959771f, 0.0006754494059985568f, \
   -0.00011747678400228192f }

__device__ __forceinline__ float softthr(float v, float thr) {
    float av = fabsf(v) - thr;
    return av > 0.f ? copysignf(av, v) : 0.f;
}

// polyphase DWT: 4 outputs r=0..3 from e[12], o[12]; uses e[r+s+1]
__device__ __forceinline__ void dwt4_eo(const float* e, const float* o,
                                        float* ca, float* cd)
{
    const float H[16] = HLIT;
    #pragma unroll
    for (int r = 0; r < 4; r++) {
        float a = 0.f, d = 0.f;
        #pragma unroll
        for (int s = 0; s < 8; s++) {
            float ev = e[r + s + 1], ov = o[r + s + 1];
            a = fmaf(H[2 * s],       ev, a);
            a = fmaf(H[2 * s + 1],   ov, a);
            d = fmaf(H[15 - 2 * s],  ev, d);
            d = fmaf(-H[14 - 2 * s], ov, d);
        }
        ca[r] = a; cd[r] = d;
    }
}

// split-array accessor with reflect
__device__ __forceinline__ float getA(const float* __restrict__ ae,
                                      const float* __restrict__ ao,
                                      int j, int n)
{
    j = (j < 0) ? (-1 - j) : j;
    j = (j >= n) ? (2 * n - 1 - j) : j;
    return (j & 1) ? ao[j >> 1] : ae[j >> 1];
}

__device__ __forceinline__ float2 dwt_scalar_eo(const float* __restrict__ ae,
                                                const float* __restrict__ ao,
                                                int n, int k)
{
    const float H[16] = HLIT;
    float a = 0.f, d = 0.f;
    #pragma unroll
    for (int t = 0; t < 16; t++) {
        float xv = getA(ae, ao, 2 * k + t - 14, n);
        a = fmaf(H[t], xv, a);
        d = fmaf((t & 1) ? -H[15 - t] : H[15 - t], xv, d);
    }
    return make_float2(a, d);
}

// ================= K_fwd: level-1 (tiled staging) + median + levels 2-4 =======
__global__ void __launch_bounds__(256, 4)
k_fwd(const float* __restrict__ x, float* __restrict__ d1g,
      float* __restrict__ d2g, float* __restrict__ d3g,
      float* __restrict__ d4g, float* __restrict__ a4g,
      float* __restrict__ thr_out)
{
    extern __shared__ float sm[];
    float* a1e = sm + F_A1E;
    float* a1o = sm + F_A1O;
    float* xe  = sm + F_XE;
    float* xo  = sm + F_XO;
    float* a2e = xe;             // staging dead after level 1
    float* a2o = xo;
    float* a3e = sm + 0;         // a1 dead after level 2
    float* a3o = sm + 1040;

    __shared__ int      s_hist[4][256];
    __shared__ unsigned s_pref;
    __shared__ int      s_rank;

    const int tid = threadIdx.x, lane = tid & 31, warp = tid >> 5;
    const int row = blockIdx.x;
    const float* xin = x + (size_t)row * LROW;
    float* pd1 = d1g + (size_t)row * S1;
    float* pd2 = d2g + (size_t)row * S2;
    float* pd3 = d3g + (size_t)row * S3;
    float* pd4 = d4g + (size_t)row * S4;
    float* pa4 = a4g + (size_t)row * S4;

    #pragma unroll
    for (int rr = 0; rr < 4; rr++) s_hist[rr][tid] = 0;
    if (tid == 0) { s_pref = 0u; s_rank = (N1 - 1) / 2; }

    // ---- level 1: 4 tiles of 2048 outputs; stage coalesced -> split smem ----
    for (int t = 0; t < 4; t++) {
        const int k0 = 2048 * t;
        const int base = 2 * k0 - 16;            // 16B aligned; base+4112 <= 16384
        for (int q = tid; q < 1028; q += 256) {
            int g = base + 4 * q;
            float v0, v1, v2, v3;
            if (g >= 0) {
                float4 v = *reinterpret_cast<const float4*>(xin + g);
                v0 = v.x; v1 = v.y; v2 = v.z; v3 = v.w;
            } else {                             // only t==0, q<4: reflect
                int m0 = -1 - g, m1 = -1 - (g + 1), m2 = -1 - (g + 2), m3 = -1 - (g + 3);
                if (g + 1 >= 0) m1 = g + 1;
                if (g + 2 >= 0) m2 = g + 2;
                if (g + 3 >= 0) m3 = g + 3;
                v0 = xin[m0]; v1 = xin[m1]; v2 = xin[m2]; v3 = xin[m3];
            }
            *reinterpret_cast<float2*>(xe + 2 * q) = make_float2(v0, v2);
            *reinterpret_cast<float2*>(xo + 2 * q) = make_float2(v1, v3);
        }
        __syncthreads();
        #pragma unroll
        for (int c = 0; c < 2; c++) {
            int p0 = 1024 * c + 4 * tid;         // tile-local output index
            float e[12], o[12];
            #pragma unroll
            for (int j = 0; j < 3; j++) {
                float4 ve = *reinterpret_cast<const float4*>(xe + p0 + 4 * j);
                float4 vo = *reinterpret_cast<const float4*>(xo + p0 + 4 * j);
                e[4*j]=ve.x; e[4*j+1]=ve.y; e[4*j+2]=ve.z; e[4*j+3]=ve.w;
                o[4*j]=vo.x; o[4*j+1]=vo.y; o[4*j+2]=vo.z; o[4*j+3]=vo.w;
            }
            float ca[4], cd[4];
            dwt4_eo(e, o, ca, cd);
            int k = k0 + p0;
            *reinterpret_cast<float4*>(pd1 + k) = make_float4(cd[0], cd[1], cd[2], cd[3]);
            *reinterpret_cast<float2*>(a1e + (k >> 1)) = make_float2(ca[0], ca[2]);
            *reinterpret_cast<float2*>(a1o + (k >> 1)) = make_float2(ca[1], ca[3]);
        }
        __syncthreads();                          // before next tile restages
    }
    // tail k = 8192..8198 from global x (reflect at right edge)
    if (tid < 7) {
        const float H[16] = HLIT;
        int k = 8192 + tid;
        float a = 0.f, d = 0.f;
        #pragma unroll
        for (int t2 = 0; t2 < 16; t2++) {
            int m = 2 * k + t2 - 14;
            if (m >= LROW) m = 2 * LROW - 1 - m;
            float xv = xin[m];
            a = fmaf(H[t2], xv, a);
            d = fmaf((t2 & 1) ? -H[15 - t2] : H[15 - t2], xv, d);
        }
        pd1[k] = d;
        if (k & 1) a1o[k >> 1] = a; else a1e[k >> 1] = a;
    }
    __syncthreads();

    // ---- exact median of |d1|: re-read own d1 (L2-hot) into regs ----
    float dreg[32];
    #pragma unroll
    for (int c = 0; c < 8; c++) {
        float4 v = *reinterpret_cast<const float4*>(pd1 + 1024 * c + 4 * tid);
        dreg[4*c] = v.x; dreg[4*c+1] = v.y; dreg[4*c+2] = v.z; dreg[4*c+3] = v.w;
    }
    float dtail = (tid < 7) ? pd1[8192 + tid] : 0.f;

    for (int b3 = 3; b3 >= 0; --b3) {
        const unsigned pref = s_pref;
        const int rank = s_rank;
        const int sh = b3 * 8;
        int* hist = s_hist[b3];
        #pragma unroll
        for (int j = 0; j < 32; j++) {
            unsigned u = __float_as_uint(fabsf(dreg[j]));
            bool mt = (b3 == 3) || ((u >> (sh + 8)) == pref);
            if (__any_sync(0xffffffffu, mt)) {
                unsigned bin = (u >> sh) & 255u;
                unsigned key = mt ? bin : 256u;
                unsigned grp = __match_any_sync(0xffffffffu, key);
                if (mt && lane == (__ffs(grp) - 1))
                    atomicAdd(&hist[bin], __popc(grp));
            }
        }
        if (tid < 7) {
            unsigned u = __float_as_uint(fabsf(dtail));
            if ((b3 == 3) || ((u >> (sh + 8)) == pref))
                atomicAdd(&hist[(u >> sh) & 255u], 1);
        }
        __syncthreads();
        if (warp == 0) {
            int base2 = lane * 8;
            int cnt[8], s = 0;
            #pragma unroll
            for (int q = 0; q < 8; q++) { cnt[q] = hist[base2 + q]; s += cnt[q]; }
            int incl = s;
            #pragma unroll
            for (int o2 = 1; o2 < 32; o2 <<= 1) {
                int t2 = __shfl_up_sync(0xffffffffu, incl, o2);
                if (lane >= o2) incl += t2;
            }
            int excl = incl - s;
            if (rank >= excl && rank < incl) {
                int acc = excl;
                #pragma unroll
                for (int q = 0; q < 8; q++) {
                    if (rank < acc + cnt[q]) {
                        s_pref = (pref << 8) | (unsigned)(base2 + q);
                        s_rank = rank - acc;
                        break;
                    }
                    acc += cnt[q];
                }
            }
        }
        __syncthreads();
    }
    if (tid == 0) {
        float med = __uint_as_float(s_pref);
        thr_out[row] = (med / 0.6745f) * 4.4054649f;   // * sqrt(2 ln 16384)
    }

    // ---- level 2: smem split a1 -> smem split a2 (in xe/xo) + d2 global ----
    #pragma unroll
    for (int c = 0; c < 4; c++) {
        int m0 = 1024 * c + 4 * tid;       // < 4096
        if (m0 >= 8) {
            float e[12], o[12];
            #pragma unroll
            for (int j = 0; j < 3; j++) {
                float4 ve = *reinterpret_cast<const float4*>(a1e + m0 - 8 + 4 * j);
                float4 vo = *reinterpret_cast<const float4*>(a1o + m0 - 8 + 4 * j);
                e[4*j]=ve.x; e[4*j+1]=ve.y; e[4*j+2]=ve.z; e[4*j+3]=ve.w;
                o[4*j]=vo.x; o[4*j+1]=vo.y; o[4*j+2]=vo.z; o[4*j+3]=vo.w;
            }
            float ca[4], cd[4];
            dwt4_eo(e, o, ca, cd);         // e[r+s+1] = a1[...], OFF matches -8 base
            *reinterpret_cast<float4*>(pd2 + m0) = make_float4(cd[0], cd[1], cd[2], cd[3]);
            *reinterpret_cast<float2*>(a2e + (m0 >> 1)) = make_float2(ca[0], ca[2]);
            *reinterpret_cast<float2*>(a2o + (m0 >> 1)) = make_float2(ca[1], ca[3]);
        } else {
            #pragma unroll
            for (int r = 0; r < 4; r++) {
                int m = m0 + r;
                float2 ad = dwt_scalar_eo(a1e, a1o, N1, m);
                pd2[m] = ad.y;
                if (m & 1) a2o[m >> 1] = ad.x; else a2e[m >> 1] = ad.x;
            }
        }
    }
    {   int m = 4096 + tid;                // tail 4096..4106
        if (m < N2) {
            float2 ad = dwt_scalar_eo(a1e, a1o, N1, m);
            pd2[m] = ad.y;
            if (m & 1) a2o[m >> 1] = ad.x; else a2e[m >> 1] = ad.x;
        }
    }
    __syncthreads();

    // ---- level 3: a2 -> a3 (overlaying dead a1) + d3 global ----
    #pragma unroll
    for (int c = 0; c < 2; c++) {
        int m0 = 1024 * c + 4 * tid;       // < 2048
        if (m0 >= 8) {
            float e[12], o[12];
            #pragma unroll
            for (int j = 0; j < 3; j++) {
                float4 ve = *reinterpret_cast<const float4*>(a2e + m0 - 8 + 4 * j);
                float4 vo = *reinterpret_cast<const float4*>(a2o + m0 - 8 + 4 * j);
                e[4*j]=ve.x; e[4*j+1]=ve.y; e[4*j+2]=ve.z; e[4*j+3]=ve.w;
                o[4*j]=vo.x; o[4*j+1]=vo.y; o[4*j+2]=vo.z; o[4*j+3]=vo.w;
            }
            float ca[4], cd[4];
            dwt4_eo(e, o, ca, cd);
            *reinterpret_cast<float4*>(pd3 + m0) = make_float4(cd[0], cd[1], cd[2], cd[3]);
            *reinterpret_cast<float2*>(a3e + (m0 >> 1)) = make_float2(ca[0], ca[2]);
            *reinterpret_cast<float2*>(a3o + (m0 >> 1)) = make_float2(ca[1], ca[3]);
        } else {
            #pragma unroll
            for (int r = 0; r < 4; r++) {
                int m = m0 + r;
                float2 ad = dwt_scalar_eo(a2e, a2o, N2, m);
                pd3[m] = ad.y;
                if (m & 1) a3o[m >> 1] = ad.x; else a3e[m >> 1] = ad.x;
            }
        }
    }
    {   int m = 2048 + tid;                // tail 2048..2060
        if (m < N3) {
            float2 ad = dwt_scalar_eo(a2e, a2o, N2, m);
            pd3[m] = ad.y;
            if (m & 1) a3o[m >> 1] = ad.x; else a3e[m >> 1] = ad.x;
        }
    }
    __syncthreads();

    // ---- level 4: a3 -> a4/d4 global ----
    {
        int m0 = 4 * tid;                  // < 1024
        if (m0 >= 8) {
            float e[12], o[12];
            #pragma unroll
            for (int j = 0; j < 3; j++) {
                float4 ve = *reinterpret_cast<const float4*>(a3e + m0 - 8 + 4 * j);
                float4 vo = *reinterpret_cast<const float4*>(a3o + m0 - 8 + 4 * j);
                e[4*j]=ve.x; e[4*j+1]=ve.y; e[4*j+2]=ve.z; e[4*j+3]=ve.w;
                o[4*j]=vo.x; o[4*j+1]=vo.y; o[4*j+2]=vo.z; o[4*j+3]=vo.w;
            }
            float ca[4], cd[4];
            dwt4_eo(e, o, ca, cd);
            *reinterpret_cast<float4*>(pa4 + m0) = make_float4(ca[0], ca[1], ca[2], ca[3]);
            *reinterpret_cast<float4*>(pd4 + m0) = make_float4(cd[0], cd[1], cd[2], cd[3]);
        } else {
            #pragma unroll
            for (int r = 0; r < 4; r++) {
                int m = m0 + r;
                float2 ad = dwt_scalar_eo(a3e, a3o, N3, m);
                pa4[m] = ad.x; pd4[m] = ad.y;
            }
        }
        int m = 1024 + tid;                // tail 1024..1037
        if (m < N4) {
            float2 ad = dwt_scalar_eo(a3e, a3o, N3, m);
            pa4[m] = ad.x; pd4[m] = ad.y;
        }
    }
}

// ---------- idwt core ----------
__device__ __forceinline__ void idwt4(const float* a, const float* d, float* o) {
    const float H[16] = HLIT;
    #pragma unroll
    for (int pp = 0; pp < 4; pp++) {
        float e = 0.f, od = 0.f;
        #pragma unroll
        for (int s = 0; s < 8; s++) {
            e  = fmaf(H[14 - 2 * s], a[pp + s], e);
            e  = fmaf(H[2 * s + 1],  d[pp + s], e);
            od = fmaf(H[15 - 2 * s], a[pp + s], od);
            od = fmaf(-H[2 * s],     d[pp + s], od);
        }
        o[2*pp] = e; o[2*pp+1] = od;
    }
}

__device__ __forceinline__ void idwt_pass(const float* __restrict__ ca,
                                          const float* __restrict__ cd,
                                          int n, float thr,
                                          float* __restrict__ rec, int tid)
{
    int plim = n - 7;
    for (int p0 = 4 * tid; p0 < plim; p0 += 1024) {
        float a[12], d[12];
        if (p0 + 12 <= n) {
            #pragma unroll
            for (int j = 0; j < 3; j++) {
                float4 va = *reinterpret_cast<const float4*>(ca + p0 + 4 * j);
                float4 vd = *reinterpret_cast<const float4*>(cd + p0 + 4 * j);
                a[4*j] = va.x; a[4*j+1] = va.y; a[4*j+2] = va.z; a[4*j+3] = va.w;
                d[4*j] = vd.x; d[4*j+1] = vd.y; d[4*j+2] = vd.z; d[4*j+3] = vd.w;
            }
        } else {
            #pragma unroll
            for (int j = 0; j < 12; j++) {
                int q = p0 + j; if (q > n - 1) q = n - 1;
                a[j] = ca[q]; d[j] = cd[q];
            }
        }
        #pragma unroll
        for (int j = 0; j < 12; j++) d[j] = softthr(d[j], thr);
        float o[8];
        idwt4(a, d, o);
        if (p0 + 4 <= plim) {
            *reinterpret_cast<float4*>(rec + 2 * p0)     = make_float4(o[0], o[1], o[2], o[3]);
            *reinterpret_cast<float4*>(rec + 2 * p0 + 4) = make_float4(o[4], o[5], o[6], o[7]);
        } else {
            #pragma unroll
            for (int pp = 0; pp < 4; pp++)
                if (p0 + pp < plim) {
                    rec[2 * (p0 + pp)]     = o[2*pp];
                    rec[2 * (p0 + pp) + 1] = o[2*pp+1];
                }
        }
    }
}

// ============ K_inv: IDWT 4 -> 3 -> 2 -> 1, final level streams to out =======
__global__ void __launch_bounds__(256, 4)
k_inv(const float* __restrict__ a4g, const float* __restrict__ d4g,
      const float* __restrict__ d3g, const float* __restrict__ d2g,
      const float* __restrict__ d1g, const float* __restrict__ thr_arr,
      float* __restrict__ out)
{
    extern __shared__ float sm[];
    float* REC = sm;
    float* R4  = sm;
    float* R3  = sm + OFF_HI;

    const int tid = threadIdx.x;
    const int row = blockIdx.x;
    const float thr = __ldg(thr_arr + row);
    const float* pa4 = a4g + (size_t)row * S4;
    const float* pd4 = d4g + (size_t)row * S4;
    const float* pd3 = d3g + (size_t)row * S3;
    const float* pd2 = d2g + (size_t)row * S2;
    const float* pd1 = d1g + (size_t)row * S1;
    float* orow = out + (size_t)row * LROW;

    idwt_pass(pa4, pd4, N4, thr, R4, tid);   __syncthreads();
    idwt_pass(R4,  pd3, N3, thr, R3, tid);   __syncthreads();
    idwt_pass(R3,  pd2, N2, thr, REC, tid);  __syncthreads();
    idwt_pass(REC, pd1, N1, thr, orow, tid);
}

extern "C" void kernel_launch(void* const* d_in, const int* in_sizes, int n_in,
                              void* d_out, int out_size)
{
    const float* x = (const float*)d_in[0];
    float* out = (float*)d_out;
    int rows = in_sizes[0] / LROW;   // 2048

    float *d1, *d2, *d3, *d4, *a4, *thr;
    cudaGetSymbolAddress((void**)&d1, g_d1);
    cudaGetSymbolAddress((void**)&d2, g_d2);
    cudaGetSymbolAddress((void**)&d3, g_d3);
    cudaGetSymbolAddress((void**)&d4, g_d4);
    cudaGetSymbolAddress((void**)&a4, g_a4);
    cudaGetSymbolAddress((void**)&thr, g_thr);

    cudaFuncSetAttribute(k_fwd, cudaFuncAttributeMaxDynamicSharedMemorySize, SM_FWD_BYTES);
    cudaFuncSetAttribute(k_inv, cudaFuncAttributeMaxDynamicSharedMemorySize, SM_INV_BYTES);

    k_fwd<<<rows, 256, SM_FWD_BYTES>>>(x, d1, d2, d3, d4, a4, thr);
    k_inv<<<rows, 256, SM_INV_BYTES>>>(a4, d4, d3, d2, d1, thr, out);
}

// round 10
// speedup vs baseline: 1.0226x; 1.0226x over previous
#include <cuda_runtime.h>

#define LROW 16384
#define N1 8199
#define N2 4107
#define N3 2061
#define N4 1038
#define ROWS_MAX 2048

// global scratch row strides (floats, multiples of 4)
#define S1   8200
#define S1EO 8208      // split a1: e at +0 (4100 used), o at +4104 (4100 used)
#define A1O  4104
#define S2   4112
#define S3   2064
#define S4   1040

__device__ float g_a1[(size_t)ROWS_MAX * S1EO];
__device__ float g_d1[(size_t)ROWS_MAX * S1];
__device__ float g_d2[(size_t)ROWS_MAX * S2];
__device__ float g_d3[(size_t)ROWS_MAX * S3];
__device__ float g_d4[(size_t)ROWS_MAX * S4];
__device__ float g_a4[(size_t)ROWS_MAX * S4];
__device__ float g_thr[ROWS_MAX];

#define HLIT { \
    0.05441584224308161f,    0.3128715909144659f,    0.6756307362980128f, \
    0.5853546836548691f,    -0.015829105256023893f, -0.2840155429624281f, \
    0.00047248457399797254f, 0.128747426620186f,    -0.01736930100202211f, \
   -0.04408825393106472f,    0.013981027917015516f,  0.008746094047015655f, \
   -0.00487035299301066f,   -0.0003917403729959771f, 0.0006754494059985568f, \
   -0.00011747678400228192f }

__device__ __forceinline__ float softthr(float v, float thr) {
    float av = fabsf(v) - thr;
    return av > 0.f ? copysignf(av, v) : 0.f;
}

// polyphase DWT: 4 outputs r=0..3 from e[12], o[12]; uses e[r+s+1]
__device__ __forceinline__ void dwt4_eo(const float* e, const float* o,
                                        float* ca, float* cd)
{
    const float H[16] = HLIT;
    #pragma unroll
    for (int r = 0; r < 4; r++) {
        float a = 0.f, d = 0.f;
        #pragma unroll
        for (int s = 0; s < 8; s++) {
            float ev = e[r + s + 1], ov = o[r + s + 1];
            a = fmaf(H[2 * s],       ev, a);
            a = fmaf(H[2 * s + 1],   ov, a);
            d = fmaf(H[15 - 2 * s],  ev, d);
            d = fmaf(-H[14 - 2 * s], ov, d);
        }
        ca[r] = a; cd[r] = d;
    }
}

// split-array accessor with reflect
__device__ __forceinline__ float getA(const float* __restrict__ ae,
                                      const float* __restrict__ ao,
                                      int j, int n)
{
    j = (j < 0) ? (-1 - j) : j;
    j = (j >= n) ? (2 * n - 1 - j) : j;
    return (j & 1) ? ao[j >> 1] : ae[j >> 1];
}

__device__ __forceinline__ float2 dwt_scalar_eo(const float* __restrict__ ae,
                                                const float* __restrict__ ao,
                                                int n, int k)
{
    const float H[16] = HLIT;
    float a = 0.f, d = 0.f;
    #pragma unroll
    for (int t = 0; t < 16; t++) {
        float xv = getA(ae, ao, 2 * k + t - 14, n);
        a = fmaf(H[t], xv, a);
        d = fmaf((t & 1) ? -H[15 - t] : H[15 - t], xv, d);
    }
    return make_float2(a, d);
}

// ===================== K1: level-1 DWT, staged + polyphase ====================
// grid (2, rows); block bx handles outputs [4096*bx, ...). Stages x with
// reflection into split xe/xo so ALL outputs use the uniform smem path.
__global__ void __launch_bounds__(256, 4)
k_l1(const float* __restrict__ x, float* __restrict__ a1g,
     float* __restrict__ d1g)
{
    __shared__ alignas(16) float xe[4112];
    __shared__ alignas(16) float xo[4112];

    const int tid = threadIdx.x;
    const int bx  = blockIdx.x;                // 0..1
    const int row = blockIdx.y;
    const int k0  = 4096 * bx;
    const float* xin = x + (size_t)row * LROW;
    float* pae = a1g + (size_t)row * S1EO;
    float* pao = pae + A1O;
    float* pd1 = d1g + (size_t)row * S1;

    // ---- stage x[base .. base+8224) with reflect, deinterleave to xe/xo ----
    const int base = 2 * k0 - 16;              // 16B aligned
    for (int q = tid; q < 2056; q += 256) {
        int g = base + 4 * q;
        float v0, v1, v2, v3;
        if (g >= 0 && g + 4 <= LROW) {
            float4 v = *reinterpret_cast<const float4*>(xin + g);
            v0 = v.x; v1 = v.y; v2 = v.z; v3 = v.w;
        } else {                               // left edge (bx0) / right edge (bx1)
            int m0 = g, m1 = g + 1, m2 = g + 2, m3 = g + 3;
            m0 = (m0 < 0) ? (-1 - m0) : ((m0 >= LROW) ? 2 * LROW - 1 - m0 : m0);
            m1 = (m1 < 0) ? (-1 - m1) : ((m1 >= LROW) ? 2 * LROW - 1 - m1 : m1);
            m2 = (m2 < 0) ? (-1 - m2) : ((m2 >= LROW) ? 2 * LROW - 1 - m2 : m2);
            m3 = (m3 < 0) ? (-1 - m3) : ((m3 >= LROW) ? 2 * LROW - 1 - m3 : m3);
            v0 = xin[m0]; v1 = xin[m1]; v2 = xin[m2]; v3 = xin[m3];
        }
        *reinterpret_cast<float2*>(xe + 2 * q) = make_float2(v0, v2);
        *reinterpret_cast<float2*>(xo + 2 * q) = make_float2(v1, v3);
    }
    __syncthreads();

    // ---- 16 outputs/thread, uniform conflict-free polyphase ----
    #pragma unroll
    for (int c = 0; c < 4; c++) {
        int p0 = 1024 * c + 4 * tid;           // local output index, < 4096
        float e[12], o[12];
        #pragma unroll
        for (int j = 0; j < 3; j++) {
            float4 ve = *reinterpret_cast<const float4*>(xe + p0 + 4 * j);
            float4 vo = *reinterpret_cast<const float4*>(xo + p0 + 4 * j);
            e[4*j]=ve.x; e[4*j+1]=ve.y; e[4*j+2]=ve.z; e[4*j+3]=ve.w;
            o[4*j]=vo.x; o[4*j+1]=vo.y; o[4*j+2]=vo.z; o[4*j+3]=vo.w;
        }
        float ca[4], cd[4];
        dwt4_eo(e, o, ca, cd);
        int k = k0 + p0;
        *reinterpret_cast<float4*>(pd1 + k) = make_float4(cd[0], cd[1], cd[2], cd[3]);
        *reinterpret_cast<float2*>(pae + (k >> 1)) = make_float2(ca[0], ca[2]);
        *reinterpret_cast<float2*>(pao + (k >> 1)) = make_float2(ca[1], ca[3]);
    }
    // tail: global outputs 8192..8198 (block 1 only), still from smem
    if (bx == 1 && tid < 7) {
        const float H[16] = HLIT;
        int p = 4096 + tid;                    // e index max p+8 = 4110 < 4112
        float a = 0.f, d = 0.f;
        #pragma unroll
        for (int s = 0; s < 8; s++) {
            float ev = xe[p + s + 1], ov = xo[p + s + 1];
            a = fmaf(H[2 * s],       ev, a);
            a = fmaf(H[2 * s + 1],   ov, a);
            d = fmaf(H[15 - 2 * s],  ev, d);
            d = fmaf(-H[14 - 2 * s], ov, d);
        }
        int k = k0 + p;                        // 8192..8198
        pd1[k] = d;
        if (k & 1) pao[k >> 1] = a; else pae[k >> 1] = a;
    }
}

// ===================== K2: fused DWT levels 2-4 (block per row, polyphase) =====
__global__ void __launch_bounds__(256, 4)
k_mid234(const float* __restrict__ a1g, float* __restrict__ d2g,
         float* __restrict__ d3g, float* __restrict__ d4g,
         float* __restrict__ a4g)
{
    __shared__ alignas(16) float a2e[2056], a2o[2056];
    __shared__ alignas(16) float a3e[1032], a3o[1032];

    const int tid = threadIdx.x;
    const int row = blockIdx.x;
    const float* pae = a1g + (size_t)row * S1EO;
    const float* pao = pae + A1O;
    float* pd2 = d2g + (size_t)row * S2;
    float* pd3 = d3g + (size_t)row * S3;
    float* pd4 = d4g + (size_t)row * S4;
    float* pa4 = a4g + (size_t)row * S4;

    // ---- level 2: global split a1 -> smem split a2 + d2 global ----
    #pragma unroll
    for (int c = 0; c < 4; c++) {
        int m0 = 1024 * c + 4 * tid;
        if (m0 >= 8) {
            float e[12], o[12];
            #pragma unroll
            for (int j = 0; j < 3; j++) {
                float4 ve = *reinterpret_cast<const float4*>(pae + m0 - 8 + 4 * j);
                float4 vo = *reinterpret_cast<const float4*>(pao + m0 - 8 + 4 * j);
                e[4*j]=ve.x; e[4*j+1]=ve.y; e[4*j+2]=ve.z; e[4*j+3]=ve.w;
                o[4*j]=vo.x; o[4*j+1]=vo.y; o[4*j+2]=vo.z; o[4*j+3]=vo.w;
            }
            float ca[4], cd[4];
            dwt4_eo(e, o, ca, cd);
            *reinterpret_cast<float4*>(pd2 + m0) = make_float4(cd[0], cd[1], cd[2], cd[3]);
            *reinterpret_cast<float2*>(a2e + (m0 >> 1)) = make_float2(ca[0], ca[2]);
            *reinterpret_cast<float2*>(a2o + (m0 >> 1)) = make_float2(ca[1], ca[3]);
        } else {
            #pragma unroll
            for (int r = 0; r < 4; r++) {
                int m = m0 + r;
                float2 ad = dwt_scalar_eo(pae, pao, N1, m);
                pd2[m] = ad.y;
                if (m & 1) a2o[m >> 1] = ad.x; else a2e[m >> 1] = ad.x;
            }
        }
    }
    {   int m = 4096 + tid;
        if (m < N2) {
            float2 ad = dwt_scalar_eo(pae, pao, N1, m);
            pd2[m] = ad.y;
            if (m & 1) a2o[m >> 1] = ad.x; else a2e[m >> 1] = ad.x;
        }
    }
    __syncthreads();

    // ---- level 3: a2 -> a3 + d3 ----
    #pragma unroll
    for (int c = 0; c < 2; c++) {
        int m0 = 1024 * c + 4 * tid;
        if (m0 >= 8) {
            float e[12], o[12];
            #pragma unroll
            for (int j = 0; j < 3; j++) {
                float4 ve = *reinterpret_cast<const float4*>(a2e + m0 - 8 + 4 * j);
                float4 vo = *reinterpret_cast<const float4*>(a2o + m0 - 8 + 4 * j);
                e[4*j]=ve.x; e[4*j+1]=ve.y; e[4*j+2]=ve.z; e[4*j+3]=ve.w;
                o[4*j]=vo.x; o[4*j+1]=vo.y; o[4*j+2]=vo.z; o[4*j+3]=vo.w;
            }
            float ca[4], cd[4];
            dwt4_eo(e, o, ca, cd);
            *reinterpret_cast<float4*>(pd3 + m0) = make_float4(cd[0], cd[1], cd[2], cd[3]);
            *reinterpret_cast<float2*>(a3e + (m0 >> 1)) = make_float2(ca[0], ca[2]);
            *reinterpret_cast<float2*>(a3o + (m0 >> 1)) = make_float2(ca[1], ca[3]);
        } else {
            #pragma unroll
            for (int r = 0; r < 4; r++) {
                int m = m0 + r;
                float2 ad = dwt_scalar_eo(a2e, a2o, N2, m);
                pd3[m] = ad.y;
                if (m & 1) a3o[m >> 1] = ad.x; else a3e[m >> 1] = ad.x;
            }
        }
    }
    {   int m = 2048 + tid;
        if (m < N3) {
            float2 ad = dwt_scalar_eo(a2e, a2o, N2, m);
            pd3[m] = ad.y;
            if (m & 1) a3o[m >> 1] = ad.x; else a3e[m >> 1] = ad.x;
        }
    }
    __syncthreads();

    // ---- level 4: a3 -> a4/d4 global ----
    {
        int m0 = 4 * tid;
        if (m0 >= 8) {
            float e[12], o[12];
            #pragma unroll
            for (int j = 0; j < 3; j++) {
                float4 ve = *reinterpret_cast<const float4*>(a3e + m0 - 8 + 4 * j);
                float4 vo = *reinterpret_cast<const float4*>(a3o + m0 - 8 + 4 * j);
                e[4*j]=ve.x; e[4*j+1]=ve.y; e[4*j+2]=ve.z; e[4*j+3]=ve.w;
                o[4*j]=vo.x; o[4*j+1]=vo.y; o[4*j+2]=vo.z; o[4*j+3]=vo.w;
            }
            float ca[4], cd[4];
            dwt4_eo(e, o, ca, cd);
            *reinterpret_cast<float4*>(pa4 + m0) = make_float4(ca[0], ca[1], ca[2], ca[3]);
            *reinterpret_cast<float4*>(pd4 + m0) = make_float4(cd[0], cd[1], cd[2], cd[3]);
        } else {
            #pragma unroll
            for (int r = 0; r < 4; r++) {
                int m = m0 + r;
                float2 ad = dwt_scalar_eo(a3e, a3o, N3, m);
                pa4[m] = ad.x; pd4[m] = ad.y;
            }
        }
        int m = 1024 + tid;
        if (m < N4) {
            float2 ad = dwt_scalar_eo(a3e, a3o, N3, m);
            pa4[m] = ad.x; pd4[m] = ad.y;
        }
    }
}

// ===================== K3: per-row exact median of |d1| -> thr ================
__global__ void __launch_bounds__(256, 4)
k_med(const float* __restrict__ d1g, float* __restrict__ thr_out)
{
    __shared__ int      s_hist[4][256];
    __shared__ unsigned s_pref;
    __shared__ int      s_rank;

    const int tid = threadIdx.x, lane = tid & 31, warp = tid >> 5;
    const float* pd = d1g + (size_t)blockIdx.x * S1;

    #pragma unroll
    for (int rr = 0; rr < 4; rr++) s_hist[rr][tid] = 0;
    if (tid == 0) { s_pref = 0u; s_rank = (N1 - 1) / 2; }

    float dreg[32];
    #pragma unroll
    for (int c = 0; c < 8; c++) {
        float4 v = *reinterpret_cast<const float4*>(pd + 1024 * c + 4 * tid);
        dreg[4*c] = v.x; dreg[4*c+1] = v.y; dreg[4*c+2] = v.z; dreg[4*c+3] = v.w;
    }
    float dtail = (tid < 7) ? pd[8192 + tid] : 0.f;
    __syncthreads();

    for (int b3 = 3; b3 >= 0; --b3) {
        const unsigned pref = s_pref;
        const int rank = s_rank;
        const int sh = b3 * 8;
        int* hist = s_hist[b3];
        #pragma unroll
        for (int j = 0; j < 32; j++) {
            unsigned u = __float_as_uint(fabsf(dreg[j]));
            bool mt = (b3 == 3) || ((u >> (sh + 8)) == pref);
            if (__any_sync(0xffffffffu, mt)) {
                unsigned bin = (u >> sh) & 255u;
                unsigned key = mt ? bin : 256u;
                unsigned grp = __match_any_sync(0xffffffffu, key);
                if (mt && lane == (__ffs(grp) - 1))
                    atomicAdd(&hist[bin], __popc(grp));
            }
        }
        if (tid < 7) {
            unsigned u = __float_as_uint(fabsf(dtail));
            if ((b3 == 3) || ((u >> (sh + 8)) == pref))
                atomicAdd(&hist[(u >> sh) & 255u], 1);
        }
        __syncthreads();
        if (warp == 0) {
            int base = lane * 8;
            int cnt[8], s = 0;
            #pragma unroll
            for (int q = 0; q < 8; q++) { cnt[q] = hist[base + q]; s += cnt[q]; }
            int incl = s;
            #pragma unroll
            for (int o = 1; o < 32; o <<= 1) {
                int t2 = __shfl_up_sync(0xffffffffu, incl, o);
                if (lane >= o) incl += t2;
            }
            int excl = incl - s;
            if (rank >= excl && rank < incl) {
                int acc = excl;
                #pragma unroll
                for (int q = 0; q < 8; q++) {
                    if (rank < acc + cnt[q]) {
                        s_pref = (pref << 8) | (unsigned)(base + q);
                        s_rank = rank - acc;
                        break;
                    }
                    acc += cnt[q];
                }
            }
        }
        __syncthreads();
    }
    if (tid == 0) {
        float med = __uint_as_float(s_pref);
        thr_out[blockIdx.x] = (med / 0.6745f) * 4.4054649f;  // * sqrt(2 ln 16384)
    }
}

// ---------- idwt core ----------
__device__ __forceinline__ void idwt4(const float* a, const float* d, float* o) {
    const float H[16] = HLIT;
    #pragma unroll
    for (int pp = 0; pp < 4; pp++) {
        float e = 0.f, od = 0.f;
        #pragma unroll
        for (int s = 0; s < 8; s++) {
            e  = fmaf(H[14 - 2 * s], a[pp + s], e);
            e  = fmaf(H[2 * s + 1],  d[pp + s], e);
            od = fmaf(H[15 - 2 * s], a[pp + s], od);
            od = fmaf(-H[2 * s],     d[pp + s], od);
        }
        o[2*pp] = e; o[2*pp+1] = od;
    }
}

__device__ __forceinline__ void idwt_pass(const float* __restrict__ ca,
                                          const float* __restrict__ cd,
                                          int n, float thr,
                                          float* __restrict__ rec, int tid)
{
    int plim = n - 7;
    for (int p0 = 4 * tid; p0 < plim; p0 += 1024) {
        float a[12], d[12];
        if (p0 + 12 <= n) {
            #pragma unroll
            for (int j = 0; j < 3; j++) {
                float4 va = *reinterpret_cast<const float4*>(ca + p0 + 4 * j);
                float4 vd = *reinterpret_cast<const float4*>(cd + p0 + 4 * j);
                a[4*j] = va.x; a[4*j+1] = va.y; a[4*j+2] = va.z; a[4*j+3] = va.w;
                d[4*j] = vd.x; d[4*j+1] = vd.y; d[4*j+2] = vd.z; d[4*j+3] = vd.w;
            }
        } else {
            #pragma unroll
            for (int j = 0; j < 12; j++) {
                int q = p0 + j; if (q > n - 1) q = n - 1;
                a[j] = ca[q]; d[j] = cd[q];
            }
        }
        #pragma unroll
        for (int j = 0; j < 12; j++) d[j] = softthr(d[j], thr);
        float o[8];
        idwt4(a, d, o);
        if (p0 + 4 <= plim) {
            *reinterpret_cast<float4*>(rec + 2 * p0)     = make_float4(o[0], o[1], o[2], o[3]);
            *reinterpret_cast<float4*>(rec + 2 * p0 + 4) = make_float4(o[4], o[5], o[6], o[7]);
        } else {
            #pragma unroll
            for (int pp = 0; pp < 4; pp++)
                if (p0 + pp < plim) {
                    rec[2 * (p0 + pp)]     = o[2*pp];
                    rec[2 * (p0 + pp) + 1] = o[2*pp+1];
                }
        }
    }
}

// ============ K4: IDWT 4 -> 3 -> 2 -> 1, final level streams to out =======
#define SM_INV_FLOATS 12320
#define SM_INV_BYTES  (SM_INV_FLOATS * 4)
#define OFF_HI        8208

__global__ void __launch_bounds__(256, 4)
k_inv(const float* __restrict__ a4g, const float* __restrict__ d4g,
      const float* __restrict__ d3g, const float* __restrict__ d2g,
      const float* __restrict__ d1g, const float* __restrict__ thr_arr,
      float* __restrict__ out)
{
    extern __shared__ float sm[];
    float* REC = sm;
    float* R4  = sm;
    float* R3  = sm + OFF_HI;

    const int tid = threadIdx.x;
    const int row = blockIdx.x;
    const float thr = __ldg(thr_arr + row);
    const float* pa4 = a4g + (size_t)row * S4;
    const float* pd4 = d4g + (size_t)row * S4;
    const float* pd3 = d3g + (size_t)row * S3;
    const float* pd2 = d2g + (size_t)row * S2;
    const float* pd1 = d1g + (size_t)row * S1;
    float* orow = out + (size_t)row * LROW;

    idwt_pass(pa4, pd4, N4, thr, R4, tid);   __syncthreads();
    idwt_pass(R4,  pd3, N3, thr, R3, tid);   __syncthreads();
    idwt_pass(R3,  pd2, N2, thr, REC, tid);  __syncthreads();
    idwt_pass(REC, pd1, N1, thr, orow, tid);
}

extern "C" void kernel_launch(void* const* d_in, const int* in_sizes, int n_in,
                              void* d_out, int out_size)
{
    const float* x = (const float*)d_in[0];
    float* out = (float*)d_out;
    int rows = in_sizes[0] / LROW;   // 2048

    float *a1, *d1, *d2, *d3, *d4, *a4, *thr;
    cudaGetSymbolAddress((void**)&a1, g_a1);
    cudaGetSymbolAddress((void**)&d1, g_d1);
    cudaGetSymbolAddress((void**)&d2, g_d2);
    cudaGetSymbolAddress((void**)&d3, g_d3);
    cudaGetSymbolAddress((void**)&d4, g_d4);
    cudaGetSymbolAddress((void**)&a4, g_a4);
    cudaGetSymbolAddress((void**)&thr, g_thr);

    cudaFuncSetAttribute(k_inv, cudaFuncAttributeMaxDynamicSharedMemorySize, SM_INV_BYTES);

    // order chosen so ncu (-s 5) captures k_mid234 on the 6th launch
    k_l1    <<<dim3(2, rows), 256>>>(x, a1, d1);
    k_mid234<<<rows, 256>>>(a1, d2, d3, d4, a4);
    k_med   <<<rows, 256>>>(d1, thr);
    k_inv   <<<rows, 256, SM_INV_BYTES>>>(a4, d4, d3, d2, d1, thr, out);
}